// round 2
// baseline (speedup 1.0000x reference)
#include <cuda_runtime.h>
#include <cuda_bf16.h>
#include <math.h>

#define NV 4000
#define NL 8000          // 2*NV literals
#define NC 16800
#define NE 50400         // NC*3 edges
#define FM 256
#define ROUNDS 32

// ---------------------------------------------------------------------------
// Scratch (static device globals; no runtime allocation allowed)
// ---------------------------------------------------------------------------
__device__ float g_lh[NL * FM];
__device__ float g_lc[NL * FM];
__device__ float g_ch[NC * FM];
__device__ float g_cc[NC * FM];
__device__ float g_buf1[NC * FM];
__device__ float g_buf2[NC * FM];
__device__ float g_msgc[NC * FM];
__device__ float g_zc[NC * 4 * FM];
__device__ float g_xl[NL * 2 * FM];
__device__ float g_zl[NL * 4 * FM];
__device__ float g_xv[NV * 2 * FM];
__device__ float g_v1[NV * 2 * FM];
__device__ float g_v2[NV * 2 * FM];
__device__ float g_logits[NV];
__device__ float g_loss;

__device__ int g_lit[NE];        // literal index per edge (0..NL-1)
__device__ int g_cnt[NL];        // per-literal degree / fill cursor
__device__ int g_off[NL + 1];    // CSR offsets
__device__ int g_ledges[NE];     // CSR edge lists per literal

// ---------------------------------------------------------------------------
// Edge preprocessing
// ---------------------------------------------------------------------------
__global__ void edge_prep_kernel(const int* __restrict__ lits) {
    int e = blockIdx.x * blockDim.x + threadIdx.x;
    if (e >= NE) return;
    int v = lits[e];
    int va = (v > 0 ? v : -v) - 1;
    g_lit[e] = (v > 0) ? va : (NV + va);
}

__global__ void zero_cnt_kernel() {
    int i = blockIdx.x * blockDim.x + threadIdx.x;
    if (i < NL) g_cnt[i] = 0;
}

__global__ void count_kernel() {
    int e = blockIdx.x * blockDim.x + threadIdx.x;
    if (e < NE) atomicAdd(&g_cnt[g_lit[e]], 1);
}

// single-block exclusive scan of g_cnt -> g_off   (8000 entries, 1024 threads x chunk 8)
__global__ void scan_kernel() {
    __shared__ int part[1024];
    const int t = threadIdx.x;
    const int CH = 8;
    int base = t * CH;
    int local[CH];
    int s = 0;
    #pragma unroll
    for (int i = 0; i < CH; i++) {
        int idx = base + i;
        int v = (idx < NL) ? g_cnt[idx] : 0;
        local[i] = s;
        s += v;
    }
    part[t] = s;
    __syncthreads();
    // Hillis-Steele inclusive scan
    for (int d = 1; d < 1024; d <<= 1) {
        int v = (t >= d) ? part[t - d] : 0;
        __syncthreads();
        part[t] += v;
        __syncthreads();
    }
    int off = (t == 0) ? 0 : part[t - 1];
    #pragma unroll
    for (int i = 0; i < CH; i++) {
        int idx = base + i;
        if (idx < NL) g_off[idx] = off + local[i];
    }
    if (t == 1023) g_off[NL] = part[1023];
}

__global__ void fill_kernel() {
    int e = blockIdx.x * blockDim.x + threadIdx.x;
    if (e >= NE) return;
    int l = g_lit[e];
    int pos = atomicAdd(&g_cnt[l], 1);
    g_ledges[g_off[l] + pos] = e;
}

// make per-literal edge order deterministic (sorted ascending)
__global__ void sort_kernel() {
    int l = blockIdx.x * blockDim.x + threadIdx.x;
    if (l >= NL) return;
    int beg = g_off[l], end = g_off[l + 1];
    for (int i = beg + 1; i < end; i++) {
        int key = g_ledges[i];
        int j = i - 1;
        while (j >= beg && g_ledges[j] > key) {
            g_ledges[j + 1] = g_ledges[j];
            j--;
        }
        g_ledges[j + 1] = key;
    }
}

__global__ void init_state_kernel(const float* __restrict__ Li,
                                  const float* __restrict__ Ci) {
    int idx = blockIdx.x * blockDim.x + threadIdx.x;
    const float inv = 0.0625f;  // 1/sqrt(256)
    if (idx < NL * FM) {
        g_lh[idx] = Li[idx & (FM - 1)] * inv;
        g_lc[idx] = 0.f;
    }
    if (idx < NC * FM) {
        g_ch[idx] = Ci[idx & (FM - 1)] * inv;
        g_cc[idx] = 0.f;
    }
    if (idx == 0) g_loss = 0.f;
}

// ---------------------------------------------------------------------------
// SGEMM: C[M,N] = A[M,K] @ B[K,N] (+bias) (+=C) (relu)
// BM=128 BN=64 BK=8, 256 threads, 8x4 register tile.
// Requires: K % 8 == 0, N % 64 == 0 (true for all call sites).
// ---------------------------------------------------------------------------
#define GF_RELU 1
#define GF_ACC  2

__global__ __launch_bounds__(256)
void sgemm_kernel(const float* __restrict__ A, const float* __restrict__ B,
                  const float* __restrict__ bias, float* __restrict__ C,
                  int M, int N, int K, int flags) {
    const int BM = 128, BN = 64, BK = 8, TM = 8, TN = 4;
    __shared__ float As[BK][BM];
    __shared__ float Bs[BK][BN];

    const int tid = threadIdx.x;
    const int bm = blockIdx.y * BM;
    const int bn = blockIdx.x * BN;
    const int tx = tid & 15;   // 16 col-groups * TN=4 -> 64
    const int ty = tid >> 4;   // 16 row-groups * TM=8 -> 128

    const int a_row = tid >> 1;          // 0..127
    const int a_col = (tid & 1) * 4;     // 0 or 4
    const int b_row = tid >> 5;          // 0..7
    const int b_col = (tid & 31) * 2;    // 0..62

    float acc[TM][TN];
    #pragma unroll
    for (int i = 0; i < TM; i++)
        #pragma unroll
        for (int j = 0; j < TN; j++) acc[i][j] = 0.f;

    for (int k0 = 0; k0 < K; k0 += BK) {
        float4 av = make_float4(0.f, 0.f, 0.f, 0.f);
        if (bm + a_row < M)
            av = *(const float4*)&A[(size_t)(bm + a_row) * K + k0 + a_col];
        As[a_col + 0][a_row] = av.x;
        As[a_col + 1][a_row] = av.y;
        As[a_col + 2][a_row] = av.z;
        As[a_col + 3][a_row] = av.w;

        float2 bv = *(const float2*)&B[(size_t)(k0 + b_row) * N + bn + b_col];
        *(float2*)&Bs[b_row][b_col] = bv;
        __syncthreads();

        #pragma unroll
        for (int k = 0; k < BK; k++) {
            float a[TM], b[TN];
            *(float4*)&a[0] = *(const float4*)&As[k][ty * TM];
            *(float4*)&a[4] = *(const float4*)&As[k][ty * TM + 4];
            *(float4*)&b[0] = *(const float4*)&Bs[k][tx * TN];
            #pragma unroll
            for (int i = 0; i < TM; i++)
                #pragma unroll
                for (int j = 0; j < TN; j++)
                    acc[i][j] = fmaf(a[i], b[j], acc[i][j]);
        }
        __syncthreads();
    }

    #pragma unroll
    for (int i = 0; i < TM; i++) {
        int r = bm + ty * TM + i;
        if (r >= M) break;
        #pragma unroll
        for (int j = 0; j < TN; j++) {
            int col = bn + tx * TN + j;
            size_t cidx = (size_t)r * N + col;
            float v = acc[i][j];
            if (bias) v += bias[col];
            if (flags & GF_ACC) v += C[cidx];
            if (flags & GF_RELU) v = fmaxf(v, 0.f);
            C[cidx] = v;
        }
    }
}

// ---------------------------------------------------------------------------
// Elementwise / gather kernels
// ---------------------------------------------------------------------------
__device__ __forceinline__ float sigm(float x) { return 1.f / (1.f + expf(-x)); }

__global__ void lstm_kernel(const float* __restrict__ z,
                            float* __restrict__ h, float* __restrict__ c, int R) {
    int idx = blockIdx.x * blockDim.x + threadIdx.x;
    if (idx >= R * FM) return;
    int r = idx / FM, f = idx - r * FM;
    const float* zr = z + (size_t)r * 4 * FM;
    float zi = zr[f], zf = zr[FM + f], zg = zr[2 * FM + f], zo = zr[3 * FM + f];
    float cv = sigm(zf) * c[idx] + sigm(zi) * tanhf(zg);
    c[idx] = cv;
    h[idx] = sigm(zo) * tanhf(cv);
}

// lc_msgs[c] = sum over clause c's 3 edges of pre[lit]
__global__ void clause_gather_kernel(const float* __restrict__ pre,
                                     float* __restrict__ out) {
    int c = blockIdx.x;
    int f = threadIdx.x;
    int e0 = c * 3;
    float s = pre[(size_t)g_lit[e0] * FM + f] +
              pre[(size_t)g_lit[e0 + 1] * FM + f] +
              pre[(size_t)g_lit[e0 + 2] * FM + f];
    out[(size_t)c * FM + f] = s;
}

// xl[l] = [ sum_{edges of l} cl_pre[clause(e)] , lh[flip(l)] ]
__global__ void lit_gather_kernel(const float* __restrict__ cl_pre,
                                  const float* __restrict__ lh,
                                  float* __restrict__ xl) {
    int l = blockIdx.x;
    int f = threadIdx.x;
    int beg = g_off[l], end = g_off[l + 1];
    float s = 0.f;
    for (int i = beg; i < end; i++) {
        int e = g_ledges[i];
        s += cl_pre[(size_t)(e / 3) * FM + f];
    }
    size_t row = (size_t)l * 2 * FM;
    xl[row + f] = s;
    int fl = (l < NV) ? (l + NV) : (l - NV);
    xl[row + FM + f] = lh[(size_t)fl * FM + f];
}

__global__ void vote_concat_kernel(const float* __restrict__ lh,
                                   float* __restrict__ xv) {
    int v = blockIdx.x;
    int f = threadIdx.x;
    size_t row = (size_t)v * 2 * FM;
    xv[row + f] = lh[(size_t)v * FM + f];
    xv[row + FM + f] = lh[(size_t)(NV + v) * FM + f];
}

// logits[v] = H[v,:] . W[:,0] + b[0]   (K=512)
__global__ void vote_out_kernel(const float* __restrict__ H,
                                const float* __restrict__ W,
                                const float* __restrict__ b) {
    int r = blockIdx.x;
    float s = 0.f;
    for (int k = threadIdx.x; k < 2 * FM; k += blockDim.x)
        s += H[(size_t)r * 2 * FM + k] * W[k];
    // block reduce (128 threads)
    for (int o = 16; o; o >>= 1) s += __shfl_down_sync(0xffffffffu, s, o);
    __shared__ float sm[4];
    if ((threadIdx.x & 31) == 0) sm[threadIdx.x >> 5] = s;
    __syncthreads();
    if (threadIdx.x == 0)
        g_logits[r] = sm[0] + sm[1] + sm[2] + sm[3] + b[0];
}

__device__ __forceinline__ float softplus_f(float x) {
    return x > 0.f ? x + log1pf(expf(-x)) : log1pf(expf(x));
}

__global__ void loss_kernel() {
    int c = blockIdx.x * blockDim.x + threadIdx.x;
    float t = 0.f;
    if (c < NC) {
        float s = 0.f;
        #pragma unroll
        for (int k = 0; k < 3; k++) {
            int lit = g_lit[c * 3 + k];
            float sign = (lit < NV) ? 1.f : -1.f;
            int var = (lit < NV) ? lit : lit - NV;
            s += softplus_f(g_logits[var] * sign);
        }
        float cv = expf(-s);
        float l = -logf(1.f - cv + 1e-8f);
        t = l * l;
    }
    for (int o = 16; o; o >>= 1) t += __shfl_down_sync(0xffffffffu, t, o);
    __shared__ float sm[8];
    if ((threadIdx.x & 31) == 0) sm[threadIdx.x >> 5] = t;
    __syncthreads();
    if (threadIdx.x < 8) {
        float v = sm[threadIdx.x];
        for (int o = 4; o; o >>= 1) v += __shfl_down_sync(0xffu, v, o);
        if (threadIdx.x == 0) atomicAdd(&g_loss, v);
    }
}

__global__ void finalize_kernel(float* __restrict__ out, int out_size) {
    int i = blockIdx.x * blockDim.x + threadIdx.x;
    if (i < NV && i < out_size) out[i] = g_logits[i];
    if (i == 0 && out_size > NV) out[NV] = g_loss / (float)ROUNDS;
}

// ---------------------------------------------------------------------------
// Host orchestration
// ---------------------------------------------------------------------------
static inline void launch_gemm(const float* A, const float* B, const float* bias,
                               float* C, int M, int N, int K, int flags) {
    dim3 grid((N + 63) / 64, (M + 127) / 128);
    sgemm_kernel<<<grid, 256>>>(A, B, bias, C, M, N, K, flags);
}

extern "C" void kernel_launch(void* const* d_in, const int* in_sizes, int n_in,
                              void* d_out, int out_size) {
    // n_vars may or may not appear as a size-1 input after clause_lits
    int base = (n_in >= 2 && in_sizes[1] == 1) ? 1 : 0;
    const int* clause_lits = (const int*)d_in[0];
    const float* P[26];
    for (int i = 0; i < 26; i++) P[i] = (const float*)d_in[1 + base + i];
    const float *L_init = P[0], *C_init = P[1];
    const float *LC_W0 = P[2], *LC_b0 = P[3], *LC_W1 = P[4], *LC_b1 = P[5],
                *LC_W2 = P[6], *LC_b2 = P[7];
    const float *CL_W0 = P[8], *CL_b0 = P[9], *CL_W1 = P[10], *CL_b1 = P[11],
                *CL_W2 = P[12], *CL_b2 = P[13];
    const float *C_Wx = P[14], *C_Wh = P[15], *C_b = P[16];
    const float *L_Wx = P[17], *L_Wh = P[18], *L_b = P[19];
    const float *V_W0 = P[20], *V_b0 = P[21], *V_W1 = P[22], *V_b1 = P[23],
                *V_W2 = P[24], *V_b2 = P[25];

    float *lh, *lc, *ch, *cc, *buf1, *buf2, *msgc, *zc, *xl, *zl, *xv, *v1, *v2;
    cudaGetSymbolAddress((void**)&lh, g_lh);
    cudaGetSymbolAddress((void**)&lc, g_lc);
    cudaGetSymbolAddress((void**)&ch, g_ch);
    cudaGetSymbolAddress((void**)&cc, g_cc);
    cudaGetSymbolAddress((void**)&buf1, g_buf1);
    cudaGetSymbolAddress((void**)&buf2, g_buf2);
    cudaGetSymbolAddress((void**)&msgc, g_msgc);
    cudaGetSymbolAddress((void**)&zc, g_zc);
    cudaGetSymbolAddress((void**)&xl, g_xl);
    cudaGetSymbolAddress((void**)&zl, g_zl);
    cudaGetSymbolAddress((void**)&xv, g_xv);
    cudaGetSymbolAddress((void**)&v1, g_v1);
    cudaGetSymbolAddress((void**)&v2, g_v2);

    // ---- preprocessing (runs every call; deterministic) ----
    edge_prep_kernel<<<(NE + 255) / 256, 256>>>(clause_lits);
    zero_cnt_kernel<<<(NL + 255) / 256, 256>>>();
    count_kernel<<<(NE + 255) / 256, 256>>>();
    scan_kernel<<<1, 1024>>>();
    zero_cnt_kernel<<<(NL + 255) / 256, 256>>>();
    fill_kernel<<<(NE + 255) / 256, 256>>>();
    sort_kernel<<<(NL + 127) / 128, 128>>>();
    init_state_kernel<<<(NC * FM + 255) / 256, 256>>>(L_init, C_init);

    // ---- 32 message-passing rounds ----
    for (int r = 0; r < ROUNDS; r++) {
        // literal -> clause MLP
        launch_gemm(lh, LC_W0, LC_b0, buf1, NL, FM, FM, GF_RELU);
        launch_gemm(buf1, LC_W1, LC_b1, buf2, NL, FM, FM, GF_RELU);
        launch_gemm(buf2, LC_W2, LC_b2, buf1, NL, FM, FM, 0);
        clause_gather_kernel<<<NC, FM>>>(buf1, msgc);

        // clause LSTM
        launch_gemm(msgc, C_Wx, C_b, zc, NC, 4 * FM, FM, 0);
        launch_gemm(ch, C_Wh, nullptr, zc, NC, 4 * FM, FM, GF_ACC);
        lstm_kernel<<<(NC * FM + 255) / 256, 256>>>(zc, ch, cc, NC);

        // clause -> literal MLP
        launch_gemm(ch, CL_W0, CL_b0, buf1, NC, FM, FM, GF_RELU);
        launch_gemm(buf1, CL_W1, CL_b1, buf2, NC, FM, FM, GF_RELU);
        launch_gemm(buf2, CL_W2, CL_b2, buf1, NC, FM, FM, 0);
        lit_gather_kernel<<<NL, FM>>>(buf1, lh, xl);

        // literal LSTM
        launch_gemm(xl, L_Wx, L_b, zl, NL, 4 * FM, 2 * FM, 0);
        launch_gemm(lh, L_Wh, nullptr, zl, NL, 4 * FM, FM, GF_ACC);
        lstm_kernel<<<(NL * FM + 255) / 256, 256>>>(zl, lh, lc, NL);

        // vote + loss
        vote_concat_kernel<<<NV, FM>>>(lh, xv);
        launch_gemm(xv, V_W0, V_b0, v1, NV, 2 * FM, 2 * FM, GF_RELU);
        launch_gemm(v1, V_W1, V_b1, v2, NV, 2 * FM, 2 * FM, GF_RELU);
        vote_out_kernel<<<NV, 128>>>(v2, V_W2, V_b2);
        loss_kernel<<<(NC + 255) / 256, 256>>>();
    }

    finalize_kernel<<<(NV + 255) / 256, 256>>>((float*)d_out, out_size);
}

// round 3
// speedup vs baseline: 1.0768x; 1.0768x over previous
#include <cuda_runtime.h>
#include <cuda_bf16.h>
#include <math.h>

#define NV 4000
#define NL 8000          // 2*NV literals
#define NC 16800
#define NE 50400         // NC*3 edges
#define FM 256
#define ROUNDS 32

// ---------------------------------------------------------------------------
// Scratch (static device globals; no runtime allocation allowed)
// ---------------------------------------------------------------------------
__device__ float g_lh[NL * FM];
__device__ float g_lc[NL * FM];
__device__ float g_ch[NC * FM];
__device__ float g_cc[NC * FM];
__device__ float g_buf1[NC * FM];
__device__ float g_buf2[NC * FM];
__device__ float g_msgc[NC * FM];
__device__ float g_zc[NC * 4 * FM];
__device__ float g_xl[NL * 2 * FM];
__device__ float g_zl[NL * 4 * FM];
__device__ float g_xv[NV * 2 * FM];
__device__ float g_v1[NV * 2 * FM];
__device__ float g_v2[NV * 2 * FM];
__device__ float g_logits[NV];
__device__ float g_loss;

__device__ int g_lit[NE];        // literal index per edge (0..NL-1)
__device__ int g_cnt[NL];        // per-literal degree / fill cursor
__device__ int g_off[NL + 1];    // CSR offsets
__device__ int g_ledges[NE];     // CSR edge lists per literal

// ---------------------------------------------------------------------------
// Edge preprocessing
// ---------------------------------------------------------------------------
__global__ void edge_prep_kernel(const int* __restrict__ lits) {
    int e = blockIdx.x * blockDim.x + threadIdx.x;
    if (e >= NE) return;
    int v = lits[e];
    int va = (v > 0 ? v : -v) - 1;
    g_lit[e] = (v > 0) ? va : (NV + va);
}

__global__ void zero_cnt_kernel() {
    int i = blockIdx.x * blockDim.x + threadIdx.x;
    if (i < NL) g_cnt[i] = 0;
}

__global__ void count_kernel() {
    int e = blockIdx.x * blockDim.x + threadIdx.x;
    if (e < NE) atomicAdd(&g_cnt[g_lit[e]], 1);
}

// single-block exclusive scan of g_cnt -> g_off   (8000 entries, 1024 threads x chunk 8)
__global__ void scan_kernel() {
    __shared__ int part[1024];
    const int t = threadIdx.x;
    const int CH = 8;
    int base = t * CH;
    int local[CH];
    int s = 0;
    #pragma unroll
    for (int i = 0; i < CH; i++) {
        int idx = base + i;
        int v = (idx < NL) ? g_cnt[idx] : 0;
        local[i] = s;
        s += v;
    }
    part[t] = s;
    __syncthreads();
    // Hillis-Steele inclusive scan
    for (int d = 1; d < 1024; d <<= 1) {
        int v = (t >= d) ? part[t - d] : 0;
        __syncthreads();
        part[t] += v;
        __syncthreads();
    }
    int off = (t == 0) ? 0 : part[t - 1];
    #pragma unroll
    for (int i = 0; i < CH; i++) {
        int idx = base + i;
        if (idx < NL) g_off[idx] = off + local[i];
    }
    if (t == 1023) g_off[NL] = part[1023];
}

__global__ void fill_kernel() {
    int e = blockIdx.x * blockDim.x + threadIdx.x;
    if (e >= NE) return;
    int l = g_lit[e];
    int pos = atomicAdd(&g_cnt[l], 1);
    g_ledges[g_off[l] + pos] = e;
}

// make per-literal edge order deterministic (sorted ascending)
__global__ void sort_kernel() {
    int l = blockIdx.x * blockDim.x + threadIdx.x;
    if (l >= NL) return;
    int beg = g_off[l], end = g_off[l + 1];
    for (int i = beg + 1; i < end; i++) {
        int key = g_ledges[i];
        int j = i - 1;
        while (j >= beg && g_ledges[j] > key) {
            g_ledges[j + 1] = g_ledges[j];
            j--;
        }
        g_ledges[j + 1] = key;
    }
}

__global__ void init_state_kernel(const float* __restrict__ Li,
                                  const float* __restrict__ Ci) {
    int idx = blockIdx.x * blockDim.x + threadIdx.x;
    const float inv = 0.0625f;  // 1/sqrt(256)
    if (idx < NL * FM) {
        g_lh[idx] = Li[idx & (FM - 1)] * inv;
        g_lc[idx] = 0.f;
    }
    if (idx < NC * FM) {
        g_ch[idx] = Ci[idx & (FM - 1)] * inv;
        g_cc[idx] = 0.f;
    }
    if (idx == 0) g_loss = 0.f;
}

// ---------------------------------------------------------------------------
// SGEMM: C[M,N] = A[M,K] @ B[K,N] (+bias) (+=C) (relu)
// BM=128 BN=64 BK=8, 256 threads, 8x4 register tile.
// Inner loop uses packed fp32 FMA (fma.rn.f32x2 -> FFMA2) with accumulators
// paired along rows: acc2[p][j] holds rows (2p, 2p+1) of column j.
// Requires: K % 8 == 0, N % 64 == 0 (true for all call sites).
// ---------------------------------------------------------------------------
#define GF_RELU 1
#define GF_ACC  2

__global__ __launch_bounds__(256)
void sgemm_kernel(const float* __restrict__ A, const float* __restrict__ B,
                  const float* __restrict__ bias, float* __restrict__ C,
                  int M, int N, int K, int flags) {
    const int BM = 128, BN = 64, BK = 8, TM = 8, TN = 4;
    __shared__ float As[BK][BM];
    __shared__ float Bs[BK][BN];

    const int tid = threadIdx.x;
    const int bm = blockIdx.y * BM;
    const int bn = blockIdx.x * BN;
    const int tx = tid & 15;   // 16 col-groups * TN=4 -> 64
    const int ty = tid >> 4;   // 16 row-groups * TM=8 -> 128

    const int a_row = tid >> 1;          // 0..127
    const int a_col = (tid & 1) * 4;     // 0 or 4
    const int b_row = tid >> 5;          // 0..7
    const int b_col = (tid & 31) * 2;    // 0..62

    // packed accumulators: pair p covers rows 2p and 2p+1 (lo = 2p, hi = 2p+1)
    unsigned long long acc2[TM / 2][TN];
    #pragma unroll
    for (int p = 0; p < TM / 2; p++)
        #pragma unroll
        for (int j = 0; j < TN; j++) acc2[p][j] = 0ull;

    for (int k0 = 0; k0 < K; k0 += BK) {
        float4 av = make_float4(0.f, 0.f, 0.f, 0.f);
        if (bm + a_row < M)
            av = *(const float4*)&A[(size_t)(bm + a_row) * K + k0 + a_col];
        As[a_col + 0][a_row] = av.x;
        As[a_col + 1][a_row] = av.y;
        As[a_col + 2][a_row] = av.z;
        As[a_col + 3][a_row] = av.w;

        float2 bv = *(const float2*)&B[(size_t)(k0 + b_row) * N + bn + b_col];
        *(float2*)&Bs[b_row][b_col] = bv;
        __syncthreads();

        #pragma unroll
        for (int k = 0; k < BK; k++) {
            // A fragment: 8 contiguous rows -> 4 packed f32x2 (no splat needed)
            ulonglong2 t0 = *(const ulonglong2*)&As[k][ty * TM];
            ulonglong2 t1 = *(const ulonglong2*)&As[k][ty * TM + 4];
            unsigned long long a2[4];
            a2[0] = t0.x; a2[1] = t0.y; a2[2] = t1.x; a2[3] = t1.y;

            // B fragment: 4 columns, splat each into both halves
            float4 bf = *(const float4*)&Bs[k][tx * TN];
            unsigned long long b2[4];
            asm("mov.b64 %0, {%1, %1};" : "=l"(b2[0]) : "r"(__float_as_uint(bf.x)));
            asm("mov.b64 %0, {%1, %1};" : "=l"(b2[1]) : "r"(__float_as_uint(bf.y)));
            asm("mov.b64 %0, {%1, %1};" : "=l"(b2[2]) : "r"(__float_as_uint(bf.z)));
            asm("mov.b64 %0, {%1, %1};" : "=l"(b2[3]) : "r"(__float_as_uint(bf.w)));

            #pragma unroll
            for (int p = 0; p < TM / 2; p++)
                #pragma unroll
                for (int j = 0; j < TN; j++)
                    asm("fma.rn.f32x2 %0, %1, %2, %0;"
                        : "+l"(acc2[p][j]) : "l"(a2[p]), "l"(b2[j]));
        }
        __syncthreads();
    }

    #pragma unroll
    for (int p = 0; p < TM / 2; p++) {
        int r0 = bm + ty * TM + 2 * p;
        #pragma unroll
        for (int j = 0; j < TN; j++) {
            unsigned int lo, hi;
            asm("mov.b64 {%0, %1}, %2;" : "=r"(lo), "=r"(hi) : "l"(acc2[p][j]));
            float v0 = __uint_as_float(lo);
            float v1 = __uint_as_float(hi);
            int col = bn + tx * TN + j;
            if (bias) { float bb = bias[col]; v0 += bb; v1 += bb; }
            if (r0 < M) {
                size_t cidx = (size_t)r0 * N + col;
                float v = v0;
                if (flags & GF_ACC) v += C[cidx];
                if (flags & GF_RELU) v = fmaxf(v, 0.f);
                C[cidx] = v;
            }
            if (r0 + 1 < M) {
                size_t cidx = (size_t)(r0 + 1) * N + col;
                float v = v1;
                if (flags & GF_ACC) v += C[cidx];
                if (flags & GF_RELU) v = fmaxf(v, 0.f);
                C[cidx] = v;
            }
        }
    }
}

// ---------------------------------------------------------------------------
// Elementwise / gather kernels
// ---------------------------------------------------------------------------
__device__ __forceinline__ float sigm(float x) { return 1.f / (1.f + expf(-x)); }

__global__ void lstm_kernel(const float* __restrict__ z,
                            float* __restrict__ h, float* __restrict__ c, int R) {
    int idx = blockIdx.x * blockDim.x + threadIdx.x;
    if (idx >= R * FM) return;
    int r = idx / FM, f = idx - r * FM;
    const float* zr = z + (size_t)r * 4 * FM;
    float zi = zr[f], zf = zr[FM + f], zg = zr[2 * FM + f], zo = zr[3 * FM + f];
    float cv = sigm(zf) * c[idx] + sigm(zi) * tanhf(zg);
    c[idx] = cv;
    h[idx] = sigm(zo) * tanhf(cv);
}

// lc_msgs[c] = sum over clause c's 3 edges of pre[lit]
__global__ void clause_gather_kernel(const float* __restrict__ pre,
                                     float* __restrict__ out) {
    int c = blockIdx.x;
    int f = threadIdx.x;
    int e0 = c * 3;
    float s = pre[(size_t)g_lit[e0] * FM + f] +
              pre[(size_t)g_lit[e0 + 1] * FM + f] +
              pre[(size_t)g_lit[e0 + 2] * FM + f];
    out[(size_t)c * FM + f] = s;
}

// xl[l] = [ sum_{edges of l} cl_pre[clause(e)] , lh[flip(l)] ]
__global__ void lit_gather_kernel(const float* __restrict__ cl_pre,
                                  const float* __restrict__ lh,
                                  float* __restrict__ xl) {
    int l = blockIdx.x;
    int f = threadIdx.x;
    int beg = g_off[l], end = g_off[l + 1];
    float s = 0.f;
    for (int i = beg; i < end; i++) {
        int e = g_ledges[i];
        s += cl_pre[(size_t)(e / 3) * FM + f];
    }
    size_t row = (size_t)l * 2 * FM;
    xl[row + f] = s;
    int fl = (l < NV) ? (l + NV) : (l - NV);
    xl[row + FM + f] = lh[(size_t)fl * FM + f];
}

__global__ void vote_concat_kernel(const float* __restrict__ lh,
                                   float* __restrict__ xv) {
    int v = blockIdx.x;
    int f = threadIdx.x;
    size_t row = (size_t)v * 2 * FM;
    xv[row + f] = lh[(size_t)v * FM + f];
    xv[row + FM + f] = lh[(size_t)(NV + v) * FM + f];
}

// logits[v] = H[v,:] . W[:,0] + b[0]   (K=512)
__global__ void vote_out_kernel(const float* __restrict__ H,
                                const float* __restrict__ W,
                                const float* __restrict__ b) {
    int r = blockIdx.x;
    float s = 0.f;
    for (int k = threadIdx.x; k < 2 * FM; k += blockDim.x)
        s += H[(size_t)r * 2 * FM + k] * W[k];
    // block reduce (128 threads)
    for (int o = 16; o; o >>= 1) s += __shfl_down_sync(0xffffffffu, s, o);
    __shared__ float sm[4];
    if ((threadIdx.x & 31) == 0) sm[threadIdx.x >> 5] = s;
    __syncthreads();
    if (threadIdx.x == 0)
        g_logits[r] = sm[0] + sm[1] + sm[2] + sm[3] + b[0];
}

__device__ __forceinline__ float softplus_f(float x) {
    return x > 0.f ? x + log1pf(expf(-x)) : log1pf(expf(x));
}

__global__ void loss_kernel() {
    int c = blockIdx.x * blockDim.x + threadIdx.x;
    float t = 0.f;
    if (c < NC) {
        float s = 0.f;
        #pragma unroll
        for (int k = 0; k < 3; k++) {
            int lit = g_lit[c * 3 + k];
            float sign = (lit < NV) ? 1.f : -1.f;
            int var = (lit < NV) ? lit : lit - NV;
            s += softplus_f(g_logits[var] * sign);
        }
        float cv = expf(-s);
        float l = -logf(1.f - cv + 1e-8f);
        t = l * l;
    }
    for (int o = 16; o; o >>= 1) t += __shfl_down_sync(0xffffffffu, t, o);
    __shared__ float sm[8];
    if ((threadIdx.x & 31) == 0) sm[threadIdx.x >> 5] = t;
    __syncthreads();
    if (threadIdx.x < 8) {
        float v = sm[threadIdx.x];
        for (int o = 4; o; o >>= 1) v += __shfl_down_sync(0xffu, v, o);
        if (threadIdx.x == 0) atomicAdd(&g_loss, v);
    }
}

__global__ void finalize_kernel(float* __restrict__ out, int out_size) {
    int i = blockIdx.x * blockDim.x + threadIdx.x;
    if (i < NV && i < out_size) out[i] = g_logits[i];
    if (i == 0 && out_size > NV) out[NV] = g_loss / (float)ROUNDS;
}

// ---------------------------------------------------------------------------
// Host orchestration
// ---------------------------------------------------------------------------
static inline void launch_gemm(const float* A, const float* B, const float* bias,
                               float* C, int M, int N, int K, int flags) {
    dim3 grid((N + 63) / 64, (M + 127) / 128);
    sgemm_kernel<<<grid, 256>>>(A, B, bias, C, M, N, K, flags);
}

extern "C" void kernel_launch(void* const* d_in, const int* in_sizes, int n_in,
                              void* d_out, int out_size) {
    // n_vars may or may not appear as a size-1 input after clause_lits
    int base = (n_in >= 2 && in_sizes[1] == 1) ? 1 : 0;
    const int* clause_lits = (const int*)d_in[0];
    const float* P[26];
    for (int i = 0; i < 26; i++) P[i] = (const float*)d_in[1 + base + i];
    const float *L_init = P[0], *C_init = P[1];
    const float *LC_W0 = P[2], *LC_b0 = P[3], *LC_W1 = P[4], *LC_b1 = P[5],
                *LC_W2 = P[6], *LC_b2 = P[7];
    const float *CL_W0 = P[8], *CL_b0 = P[9], *CL_W1 = P[10], *CL_b1 = P[11],
                *CL_W2 = P[12], *CL_b2 = P[13];
    const float *C_Wx = P[14], *C_Wh = P[15], *C_b = P[16];
    const float *L_Wx = P[17], *L_Wh = P[18], *L_b = P[19];
    const float *V_W0 = P[20], *V_b0 = P[21], *V_W1 = P[22], *V_b1 = P[23],
                *V_W2 = P[24], *V_b2 = P[25];

    float *lh, *lc, *ch, *cc, *buf1, *buf2, *msgc, *zc, *xl, *zl, *xv, *v1, *v2;
    cudaGetSymbolAddress((void**)&lh, g_lh);
    cudaGetSymbolAddress((void**)&lc, g_lc);
    cudaGetSymbolAddress((void**)&ch, g_ch);
    cudaGetSymbolAddress((void**)&cc, g_cc);
    cudaGetSymbolAddress((void**)&buf1, g_buf1);
    cudaGetSymbolAddress((void**)&buf2, g_buf2);
    cudaGetSymbolAddress((void**)&msgc, g_msgc);
    cudaGetSymbolAddress((void**)&zc, g_zc);
    cudaGetSymbolAddress((void**)&xl, g_xl);
    cudaGetSymbolAddress((void**)&zl, g_zl);
    cudaGetSymbolAddress((void**)&xv, g_xv);
    cudaGetSymbolAddress((void**)&v1, g_v1);
    cudaGetSymbolAddress((void**)&v2, g_v2);

    // ---- preprocessing (runs every call; deterministic) ----
    edge_prep_kernel<<<(NE + 255) / 256, 256>>>(clause_lits);
    zero_cnt_kernel<<<(NL + 255) / 256, 256>>>();
    count_kernel<<<(NE + 255) / 256, 256>>>();
    scan_kernel<<<1, 1024>>>();
    zero_cnt_kernel<<<(NL + 255) / 256, 256>>>();
    fill_kernel<<<(NE + 255) / 256, 256>>>();
    sort_kernel<<<(NL + 127) / 128, 128>>>();
    init_state_kernel<<<(NC * FM + 255) / 256, 256>>>(L_init, C_init);

    // ---- 32 message-passing rounds ----
    for (int r = 0; r < ROUNDS; r++) {
        // literal -> clause MLP
        launch_gemm(lh, LC_W0, LC_b0, buf1, NL, FM, FM, GF_RELU);
        launch_gemm(buf1, LC_W1, LC_b1, buf2, NL, FM, FM, GF_RELU);
        launch_gemm(buf2, LC_W2, LC_b2, buf1, NL, FM, FM, 0);
        clause_gather_kernel<<<NC, FM>>>(buf1, msgc);

        // clause LSTM
        launch_gemm(msgc, C_Wx, C_b, zc, NC, 4 * FM, FM, 0);
        launch_gemm(ch, C_Wh, nullptr, zc, NC, 4 * FM, FM, GF_ACC);
        lstm_kernel<<<(NC * FM + 255) / 256, 256>>>(zc, ch, cc, NC);

        // clause -> literal MLP
        launch_gemm(ch, CL_W0, CL_b0, buf1, NC, FM, FM, GF_RELU);
        launch_gemm(buf1, CL_W1, CL_b1, buf2, NC, FM, FM, GF_RELU);
        launch_gemm(buf2, CL_W2, CL_b2, buf1, NC, FM, FM, 0);
        lit_gather_kernel<<<NL, FM>>>(buf1, lh, xl);

        // literal LSTM
        launch_gemm(xl, L_Wx, L_b, zl, NL, 4 * FM, 2 * FM, 0);
        launch_gemm(lh, L_Wh, nullptr, zl, NL, 4 * FM, FM, GF_ACC);
        lstm_kernel<<<(NL * FM + 255) / 256, 256>>>(zl, lh, lc, NL);

        // vote + loss
        vote_concat_kernel<<<NV, FM>>>(lh, xv);
        launch_gemm(xv, V_W0, V_b0, v1, NV, 2 * FM, 2 * FM, GF_RELU);
        launch_gemm(v1, V_W1, V_b1, v2, NV, 2 * FM, 2 * FM, GF_RELU);
        vote_out_kernel<<<NV, 128>>>(v2, V_W2, V_b2);
        loss_kernel<<<(NC + 255) / 256, 256>>>();
    }

    finalize_kernel<<<(NV + 255) / 256, 256>>>((float*)d_out, out_size);
}

// round 7
// speedup vs baseline: 2.3185x; 2.1531x over previous
#include <cuda_runtime.h>
#include <cuda_bf16.h>
#include <math.h>
#include <stdint.h>

#define NV 4000
#define NL 8000          // 2*NV literals
#define NC 16800
#define NE 50400         // NC*3 edges
#define FM 256
#define ROUNDS 32

// ---------------------------------------------------------------------------
// PTX helpers (baseline ISA only: ldmatrix + mma.sync, sm_80+ features)
// ---------------------------------------------------------------------------
__device__ __forceinline__ uint32_t smem_u32(const void* p) {
    uint32_t a;
    asm("{ .reg .u64 t; cvta.to.shared.u64 t, %1; cvt.u32.u64 %0, t; }"
        : "=r"(a) : "l"(p));
    return a;
}
__device__ __forceinline__ void ldsm_x4(uint32_t& r0, uint32_t& r1,
                                        uint32_t& r2, uint32_t& r3, uint32_t a) {
    asm volatile("ldmatrix.sync.aligned.m8n8.x4.shared.b16 {%0,%1,%2,%3}, [%4];"
                 : "=r"(r0), "=r"(r1), "=r"(r2), "=r"(r3) : "r"(a));
}
__device__ __forceinline__ void ldsm_x2(uint32_t& r0, uint32_t& r1, uint32_t a) {
    asm volatile("ldmatrix.sync.aligned.m8n8.x2.shared.b16 {%0,%1}, [%2];"
                 : "=r"(r0), "=r"(r1) : "r"(a));
}
__device__ __forceinline__ void mma_bf16(float* c, const uint32_t* a,
                                         const uint32_t* b) {
    asm volatile(
        "mma.sync.aligned.m16n8k16.row.col.f32.bf16.bf16.f32 "
        "{%0,%1,%2,%3}, {%4,%5,%6,%7}, {%8,%9}, {%0,%1,%2,%3};"
        : "+f"(c[0]), "+f"(c[1]), "+f"(c[2]), "+f"(c[3])
        : "r"(a[0]), "r"(a[1]), "r"(a[2]), "r"(a[3]), "r"(b[0]), "r"(b[1]));
}

#define SWZ128(off) ((off) ^ (((off) >> 3) & 0x70))

// ---------------------------------------------------------------------------
// Scratch (static device globals)
// ---------------------------------------------------------------------------
__device__ float g_lh[NL * FM];
__device__ float g_lc[NL * FM];
__device__ float g_ch[NC * FM];
__device__ float g_cc[NC * FM];
__device__ float g_buf1[NC * FM];
__device__ float g_buf2[NC * FM];
__device__ float g_msgc[NC * FM];
__device__ float g_zc[NC * 4 * FM];
__device__ float g_xl[NL * 2 * FM];
__device__ float g_zl[NL * 4 * FM];
__device__ float g_xv[NV * 2 * FM];
__device__ float g_v1[NV * 2 * FM];
__device__ float g_v2[NV * 2 * FM];
__device__ float g_logits[NV];
__device__ float g_loss;

__device__ int g_lit[NE];
__device__ int g_cnt[NL];
__device__ int g_off[NL + 1];
__device__ int g_ledges[NE];

// weight pool: transposed [N,K] bf16, hi then lo halves
#define WTOT 2228224
__device__ __nv_bfloat16 g_wpool[2 * WTOT];

// ---------------------------------------------------------------------------
// Edge preprocessing (unchanged, known-correct)
// ---------------------------------------------------------------------------
__global__ void edge_prep_kernel(const int* __restrict__ lits) {
    int e = blockIdx.x * blockDim.x + threadIdx.x;
    if (e >= NE) return;
    int v = lits[e];
    int va = (v > 0 ? v : -v) - 1;
    g_lit[e] = (v > 0) ? va : (NV + va);
}
__global__ void zero_cnt_kernel() {
    int i = blockIdx.x * blockDim.x + threadIdx.x;
    if (i < NL) g_cnt[i] = 0;
}
__global__ void count_kernel() {
    int e = blockIdx.x * blockDim.x + threadIdx.x;
    if (e < NE) atomicAdd(&g_cnt[g_lit[e]], 1);
}
__global__ void scan_kernel() {
    __shared__ int part[1024];
    const int t = threadIdx.x;
    const int CH = 8;
    int base = t * CH;
    int local[CH];
    int s = 0;
    #pragma unroll
    for (int i = 0; i < CH; i++) {
        int idx = base + i;
        int v = (idx < NL) ? g_cnt[idx] : 0;
        local[i] = s;
        s += v;
    }
    part[t] = s;
    __syncthreads();
    for (int d = 1; d < 1024; d <<= 1) {
        int v = (t >= d) ? part[t - d] : 0;
        __syncthreads();
        part[t] += v;
        __syncthreads();
    }
    int off = (t == 0) ? 0 : part[t - 1];
    #pragma unroll
    for (int i = 0; i < CH; i++) {
        int idx = base + i;
        if (idx < NL) g_off[idx] = off + local[i];
    }
    if (t == 1023) g_off[NL] = part[1023];
}
__global__ void fill_kernel() {
    int e = blockIdx.x * blockDim.x + threadIdx.x;
    if (e >= NE) return;
    int l = g_lit[e];
    int pos = atomicAdd(&g_cnt[l], 1);
    g_ledges[g_off[l] + pos] = e;
}
__global__ void sort_kernel() {
    int l = blockIdx.x * blockDim.x + threadIdx.x;
    if (l >= NL) return;
    int beg = g_off[l], end = g_off[l + 1];
    for (int i = beg + 1; i < end; i++) {
        int key = g_ledges[i];
        int j = i - 1;
        while (j >= beg && g_ledges[j] > key) {
            g_ledges[j + 1] = g_ledges[j];
            j--;
        }
        g_ledges[j + 1] = key;
    }
}
__global__ void init_state_kernel(const float* __restrict__ Li,
                                  const float* __restrict__ Ci) {
    int idx = blockIdx.x * blockDim.x + threadIdx.x;
    const float inv = 0.0625f;
    if (idx < NL * FM) {
        g_lh[idx] = Li[idx & (FM - 1)] * inv;
        g_lc[idx] = 0.f;
    }
    if (idx < NC * FM) {
        g_ch[idx] = Ci[idx & (FM - 1)] * inv;
        g_cc[idx] = 0.f;
    }
    if (idx == 0) g_loss = 0.f;
}

// ---------------------------------------------------------------------------
// Weight split+transpose: src fp32 [K,N] -> pool hi/lo bf16 [N,K]
// ---------------------------------------------------------------------------
__global__ void wsplit_kernel(const float* __restrict__ src, int K, int N, int off) {
    int idx = blockIdx.x * blockDim.x + threadIdx.x;
    if (idx >= K * N) return;
    int k = idx / N, n = idx - k * N;
    float v = src[idx];
    __nv_bfloat16 h = __float2bfloat16_rn(v);
    __nv_bfloat16 l = __float2bfloat16_rn(v - __bfloat162float(h));
    g_wpool[off + (size_t)n * K + k] = h;
    g_wpool[WTOT + off + (size_t)n * K + k] = l;
}

// ---------------------------------------------------------------------------
// Tensor-core GEMM via mma.sync (bf16, fp32 accum, Markidis 3-term split):
//   C[M,N] = concat(A1[M,K1], A2[M,K2]) @ concat_rows(W1, W2) (+bias)(relu)
// W pre-split transposed bf16 [N,K] hi/lo. Block 128x128, BK=64.
// 8 warps, warp tile 64x32 (4 m16 x 4 n8 mma tiles).
// ---------------------------------------------------------------------------
#define GF_RELU 1
#define TG_SMEM 65536

__global__ __launch_bounds__(256)
void tgemm_kernel(const float* __restrict__ A1, int K1,
                  const __nv_bfloat16* __restrict__ B1h,
                  const __nv_bfloat16* __restrict__ B1l,
                  const float* __restrict__ A2, int K2,
                  const __nv_bfloat16* __restrict__ B2h,
                  const __nv_bfloat16* __restrict__ B2l,
                  const float* __restrict__ bias, float* __restrict__ C,
                  int M, int N, int flags) {
    extern __shared__ char smem[];
    // tiles: Ah, Al, Bh, Bl each 128 rows x 128 bytes (64 bf16) = 16 KB
    char* tAh = smem;
    char* tAl = smem + 16384;
    char* tBh = smem + 32768;
    char* tBl = smem + 49152;
    const uint32_t sAh = smem_u32(tAh);
    const uint32_t sAl = sAh + 16384, sBh = sAh + 32768, sBl = sAh + 49152;

    const int tid = threadIdx.x;
    const int wid = tid >> 5, lid = tid & 31;
    const int bm = blockIdx.y * 128;
    const int bn = blockIdx.x * 128;
    const int wm = (wid & 1) * 64;    // warp m-offset within block
    const int wn = (wid >> 1) * 32;   // warp n-offset within block

    float acc[4][4][4];
    #pragma unroll
    for (int i = 0; i < 4; i++)
        #pragma unroll
        for (int j = 0; j < 4; j++)
            #pragma unroll
            for (int q = 0; q < 4; q++) acc[i][j][q] = 0.f;

    const int nch = (K1 + K2) >> 6;
    for (int c = 0; c < nch; c++) {
        int kk = c << 6;
        const float* A = A1;
        const __nv_bfloat16 *bh = B1h, *bl = B1l;
        int ldk = K1;
        if (kk >= K1) { A = A2; bh = B2h; bl = B2l; ldk = K2; kk -= K1; }

        __syncthreads();   // protect tiles from previous iteration's readers

        // ---- stage A (fp32 -> split bf16 hi/lo, SW128) ----
        #pragma unroll
        for (int i = 0; i < 8; i++) {
            int idx = i * 256 + tid;           // 0..2047
            int row = idx >> 4;
            int c4 = (idx & 15) << 2;          // k offset 0..60
            float4 v = make_float4(0.f, 0.f, 0.f, 0.f);
            if (bm + row < M)
                v = *(const float4*)&A[(size_t)(bm + row) * ldk + kk + c4];
            __nv_bfloat16 h0 = __float2bfloat16_rn(v.x);
            __nv_bfloat16 h1 = __float2bfloat16_rn(v.y);
            __nv_bfloat16 h2 = __float2bfloat16_rn(v.z);
            __nv_bfloat16 h3 = __float2bfloat16_rn(v.w);
            __nv_bfloat162 hp0 = __halves2bfloat162(h0, h1);
            __nv_bfloat162 hp1 = __halves2bfloat162(h2, h3);
            __nv_bfloat162 lp0 = __halves2bfloat162(
                __float2bfloat16_rn(v.x - __bfloat162float(h0)),
                __float2bfloat16_rn(v.y - __bfloat162float(h1)));
            __nv_bfloat162 lp1 = __halves2bfloat162(
                __float2bfloat16_rn(v.z - __bfloat162float(h2)),
                __float2bfloat16_rn(v.w - __bfloat162float(h3)));
            uint32_t off = SWZ128((uint32_t)(row * 128 + c4 * 2));
            *(uint2*)(tAh + off) = make_uint2(*(uint32_t*)&hp0, *(uint32_t*)&hp1);
            *(uint2*)(tAl + off) = make_uint2(*(uint32_t*)&lp0, *(uint32_t*)&lp1);
        }

        // ---- stage B (pre-split bf16 [N,K], straight swizzled copy) ----
        #pragma unroll
        for (int i = 0; i < 8; i++) {
            int idx = i * 256 + tid;           // 0..2047
            int half = idx >> 10;              // 0: hi, 1: lo
            int j = idx & 1023;
            int row = j >> 3;                  // n local 0..127
            int c16 = (j & 7) << 4;            // byte offset 0..112
            const __nv_bfloat16* src =
                (half ? bl : bh) + (size_t)(bn + row) * ldk + kk + (c16 >> 1);
            uint4 v = *(const uint4*)src;
            uint32_t off = SWZ128((uint32_t)(row * 128 + c16));
            *(uint4*)((half ? tBl : tBh) + off) = v;
        }

        __syncthreads();

        // ---- compute: 4 k16 steps ----
        #pragma unroll
        for (int s = 0; s < 4; s++) {
            int kb = s * 32;   // byte offset of this k16 within the 128B row

            uint32_t ah[4][4], al[4][4], bhf[4][2], blf[4][2];
            // A fragments (m16k16 tiles): lane -> row (l%16), col half (l/16)
            int arow = (lid & 15);
            int acolb = kb + (lid >> 4) * 16;
            #pragma unroll
            for (int mt = 0; mt < 4; mt++) {
                uint32_t o = SWZ128((uint32_t)((wm + mt * 16 + arow) * 128 + acolb));
                ldsm_x4(ah[mt][0], ah[mt][1], ah[mt][2], ah[mt][3], sAh + o);
                ldsm_x4(al[mt][0], al[mt][1], al[mt][2], al[mt][3], sAl + o);
            }
            // B fragments (n8k16 tiles): lanes 0-15 supply addresses
            int brow = (lid & 7);
            int bcolb = kb + ((lid >> 3) & 1) * 16;
            #pragma unroll
            for (int nt = 0; nt < 4; nt++) {
                uint32_t o = SWZ128((uint32_t)((wn + nt * 8 + brow) * 128 + bcolb));
                ldsm_x2(bhf[nt][0], bhf[nt][1], sBh + o);
                ldsm_x2(blf[nt][0], blf[nt][1], sBl + o);
            }

            #pragma unroll
            for (int mt = 0; mt < 4; mt++)
                #pragma unroll
                for (int nt = 0; nt < 4; nt++) {
                    mma_bf16(acc[mt][nt], ah[mt], bhf[nt]);   // Ah*Bh
                    mma_bf16(acc[mt][nt], al[mt], bhf[nt]);   // Al*Bh
                    mma_bf16(acc[mt][nt], ah[mt], blf[nt]);   // Ah*Bl
                }
        }
    }

    // ---- epilogue: direct float2 stores with bias/relu ----
    #pragma unroll
    for (int mt = 0; mt < 4; mt++) {
        int r0 = bm + wm + mt * 16 + (lid >> 2);
        #pragma unroll
        for (int nt = 0; nt < 4; nt++) {
            int col = bn + wn + nt * 8 + (lid & 3) * 2;
            float bx = 0.f, by = 0.f;
            if (bias) { bx = bias[col]; by = bias[col + 1]; }
            float2 v0 = make_float2(acc[mt][nt][0] + bx, acc[mt][nt][1] + by);
            float2 v1 = make_float2(acc[mt][nt][2] + bx, acc[mt][nt][3] + by);
            if (flags & GF_RELU) {
                v0.x = fmaxf(v0.x, 0.f); v0.y = fmaxf(v0.y, 0.f);
                v1.x = fmaxf(v1.x, 0.f); v1.y = fmaxf(v1.y, 0.f);
            }
            if (r0 < M)     *(float2*)&C[(size_t)r0 * N + col] = v0;
            if (r0 + 8 < M) *(float2*)&C[(size_t)(r0 + 8) * N + col] = v1;
        }
    }
}

// ---------------------------------------------------------------------------
// Elementwise / gather kernels (unchanged, known-correct)
// ---------------------------------------------------------------------------
__device__ __forceinline__ float sigm(float x) { return 1.f / (1.f + expf(-x)); }

__global__ void lstm_kernel(const float* __restrict__ z,
                            float* __restrict__ h, float* __restrict__ c, int R) {
    int idx = blockIdx.x * blockDim.x + threadIdx.x;
    if (idx >= R * FM) return;
    int r = idx / FM, f = idx - r * FM;
    const float* zr = z + (size_t)r * 4 * FM;
    float zi = zr[f], zf = zr[FM + f], zg = zr[2 * FM + f], zo = zr[3 * FM + f];
    float cv = sigm(zf) * c[idx] + sigm(zi) * tanhf(zg);
    c[idx] = cv;
    h[idx] = sigm(zo) * tanhf(cv);
}

__global__ void clause_gather_kernel(const float* __restrict__ pre,
                                     float* __restrict__ out) {
    int c = blockIdx.x;
    int f = threadIdx.x;
    int e0 = c * 3;
    float s = pre[(size_t)g_lit[e0] * FM + f] +
              pre[(size_t)g_lit[e0 + 1] * FM + f] +
              pre[(size_t)g_lit[e0 + 2] * FM + f];
    out[(size_t)c * FM + f] = s;
}

__global__ void lit_gather_kernel(const float* __restrict__ cl_pre,
                                  const float* __restrict__ lh,
                                  float* __restrict__ xl) {
    int l = blockIdx.x;
    int f = threadIdx.x;
    int beg = g_off[l], end = g_off[l + 1];
    float s = 0.f;
    for (int i = beg; i < end; i++) {
        int e = g_ledges[i];
        s += cl_pre[(size_t)(e / 3) * FM + f];
    }
    size_t row = (size_t)l * 2 * FM;
    xl[row + f] = s;
    int fl = (l < NV) ? (l + NV) : (l - NV);
    xl[row + FM + f] = lh[(size_t)fl * FM + f];
}

__global__ void vote_concat_kernel(const float* __restrict__ lh,
                                   float* __restrict__ xv) {
    int v = blockIdx.x;
    int f = threadIdx.x;
    size_t row = (size_t)v * 2 * FM;
    xv[row + f] = lh[(size_t)v * FM + f];
    xv[row + FM + f] = lh[(size_t)(NV + v) * FM + f];
}

__global__ void vote_out_kernel(const float* __restrict__ H,
                                const float* __restrict__ W,
                                const float* __restrict__ b) {
    int r = blockIdx.x;
    float s = 0.f;
    for (int k = threadIdx.x; k < 2 * FM; k += blockDim.x)
        s += H[(size_t)r * 2 * FM + k] * W[k];
    for (int o = 16; o; o >>= 1) s += __shfl_down_sync(0xffffffffu, s, o);
    __shared__ float sm[4];
    if ((threadIdx.x & 31) == 0) sm[threadIdx.x >> 5] = s;
    __syncthreads();
    if (threadIdx.x == 0)
        g_logits[r] = sm[0] + sm[1] + sm[2] + sm[3] + b[0];
}

__device__ __forceinline__ float softplus_f(float x) {
    return x > 0.f ? x + log1pf(expf(-x)) : log1pf(expf(x));
}

__global__ void loss_kernel() {
    int c = blockIdx.x * blockDim.x + threadIdx.x;
    float t = 0.f;
    if (c < NC) {
        float s = 0.f;
        #pragma unroll
        for (int k = 0; k < 3; k++) {
            int lit = g_lit[c * 3 + k];
            float sign = (lit < NV) ? 1.f : -1.f;
            int var = (lit < NV) ? lit : lit - NV;
            s += softplus_f(g_logits[var] * sign);
        }
        float cv = expf(-s);
        float l = -logf(1.f - cv + 1e-8f);
        t = l * l;
    }
    for (int o = 16; o; o >>= 1) t += __shfl_down_sync(0xffffffffu, t, o);
    __shared__ float sm[8];
    if ((threadIdx.x & 31) == 0) sm[threadIdx.x >> 5] = t;
    __syncthreads();
    if (threadIdx.x < 8) {
        float v = sm[threadIdx.x];
        for (int o = 4; o; o >>= 1) v += __shfl_down_sync(0xffu, v, o);
        if (threadIdx.x == 0) atomicAdd(&g_loss, v);
    }
}

__global__ void finalize_kernel(float* __restrict__ out, int out_size) {
    int i = blockIdx.x * blockDim.x + threadIdx.x;
    if (i < NV && i < out_size) out[i] = g_logits[i];
    if (i == 0 && out_size > NV) out[NV] = g_loss / (float)ROUNDS;
}

// ---------------------------------------------------------------------------
// Host orchestration
// ---------------------------------------------------------------------------
static inline void launch_tg(const float* A1, int K1, const __nv_bfloat16* wp,
                             int off1, const float* A2, int K2, int off2,
                             const float* bias, float* C, int M, int N, int flags) {
    dim3 grid(N / 128, (M + 127) / 128);
    const __nv_bfloat16 *b1h = wp + off1, *b1l = wp + WTOT + off1;
    const __nv_bfloat16 *b2h = A2 ? wp + off2 : nullptr;
    const __nv_bfloat16 *b2l = A2 ? wp + WTOT + off2 : nullptr;
    tgemm_kernel<<<grid, 256, TG_SMEM>>>(A1, K1, b1h, b1l, A2, K2, b2h, b2l,
                                         bias, C, M, N, flags);
}

extern "C" void kernel_launch(void* const* d_in, const int* in_sizes, int n_in,
                              void* d_out, int out_size) {
    int base = (n_in >= 2 && in_sizes[1] == 1) ? 1 : 0;
    const int* clause_lits = (const int*)d_in[0];
    const float* P[26];
    for (int i = 0; i < 26; i++) P[i] = (const float*)d_in[1 + base + i];
    const float *L_init = P[0], *C_init = P[1];
    const float *LC_W0 = P[2], *LC_b0 = P[3], *LC_W1 = P[4], *LC_b1 = P[5],
                *LC_W2 = P[6], *LC_b2 = P[7];
    const float *CL_W0 = P[8], *CL_b0 = P[9], *CL_W1 = P[10], *CL_b1 = P[11],
                *CL_W2 = P[12], *CL_b2 = P[13];
    const float *C_Wx = P[14], *C_Wh = P[15], *C_b = P[16];
    const float *L_Wx = P[17], *L_Wh = P[18], *L_b = P[19];
    const float *V_W0 = P[20], *V_b0 = P[21], *V_W1 = P[22], *V_b1 = P[23],
                *V_W2 = P[24], *V_b2 = P[25];

    float *lh, *lc, *ch, *cc, *buf1, *buf2, *msgc, *zc, *xl, *zl, *xv, *v1, *v2;
    __nv_bfloat16* wp;
    cudaGetSymbolAddress((void**)&lh, g_lh);
    cudaGetSymbolAddress((void**)&lc, g_lc);
    cudaGetSymbolAddress((void**)&ch, g_ch);
    cudaGetSymbolAddress((void**)&cc, g_cc);
    cudaGetSymbolAddress((void**)&buf1, g_buf1);
    cudaGetSymbolAddress((void**)&buf2, g_buf2);
    cudaGetSymbolAddress((void**)&msgc, g_msgc);
    cudaGetSymbolAddress((void**)&zc, g_zc);
    cudaGetSymbolAddress((void**)&xl, g_xl);
    cudaGetSymbolAddress((void**)&zl, g_zl);
    cudaGetSymbolAddress((void**)&xv, g_xv);
    cudaGetSymbolAddress((void**)&v1, g_v1);
    cudaGetSymbolAddress((void**)&v2, g_v2);
    cudaGetSymbolAddress((void**)&wp, g_wpool);

    cudaFuncSetAttribute(tgemm_kernel, cudaFuncAttributeMaxDynamicSharedMemorySize,
                         TG_SMEM);

    // weight pool offsets ([N,K] transposed, element offsets)
    const int oLC0 = 0, oLC1 = 65536, oLC2 = 131072;
    const int oCL0 = 196608, oCL1 = 262144, oCL2 = 327680;
    const int oCWx = 393216, oCWh = 655360;
    const int oLWx = 917504, oLWh = 1441792;
    const int oVW0 = 1703936, oVW1 = 1966080;

    struct { const float* src; int K, N, off; } WS[12] = {
        {LC_W0, 256, 256, oLC0}, {LC_W1, 256, 256, oLC1}, {LC_W2, 256, 256, oLC2},
        {CL_W0, 256, 256, oCL0}, {CL_W1, 256, 256, oCL1}, {CL_W2, 256, 256, oCL2},
        {C_Wx, 256, 1024, oCWx}, {C_Wh, 256, 1024, oCWh},
        {L_Wx, 512, 1024, oLWx}, {L_Wh, 256, 1024, oLWh},
        {V_W0, 512, 512, oVW0},  {V_W1, 512, 512, oVW1},
    };
    for (int i = 0; i < 12; i++) {
        int n = WS[i].K * WS[i].N;
        wsplit_kernel<<<(n + 255) / 256, 256>>>(WS[i].src, WS[i].K, WS[i].N,
                                                WS[i].off);
    }

    // preprocessing
    edge_prep_kernel<<<(NE + 255) / 256, 256>>>(clause_lits);
    zero_cnt_kernel<<<(NL + 255) / 256, 256>>>();
    count_kernel<<<(NE + 255) / 256, 256>>>();
    scan_kernel<<<1, 1024>>>();
    zero_cnt_kernel<<<(NL + 255) / 256, 256>>>();
    fill_kernel<<<(NE + 255) / 256, 256>>>();
    sort_kernel<<<(NL + 127) / 128, 128>>>();
    init_state_kernel<<<(NC * FM + 255) / 256, 256>>>(L_init, C_init);

    for (int r = 0; r < ROUNDS; r++) {
        // literal -> clause MLP
        launch_tg(lh, 256, wp, oLC0, nullptr, 0, 0, LC_b0, buf1, NL, 256, GF_RELU);
        launch_tg(buf1, 256, wp, oLC1, nullptr, 0, 0, LC_b1, buf2, NL, 256, GF_RELU);
        launch_tg(buf2, 256, wp, oLC2, nullptr, 0, 0, LC_b2, buf1, NL, 256, 0);
        clause_gather_kernel<<<NC, FM>>>(buf1, msgc);

        // clause LSTM (fused x/h GEMM)
        launch_tg(msgc, 256, wp, oCWx, ch, 256, oCWh, C_b, zc, NC, 1024, 0);
        lstm_kernel<<<(NC * FM + 255) / 256, 256>>>(zc, ch, cc, NC);

        // clause -> literal MLP
        launch_tg(ch, 256, wp, oCL0, nullptr, 0, 0, CL_b0, buf1, NC, 256, GF_RELU);
        launch_tg(buf1, 256, wp, oCL1, nullptr, 0, 0, CL_b1, buf2, NC, 256, GF_RELU);
        launch_tg(buf2, 256, wp, oCL2, nullptr, 0, 0, CL_b2, buf1, NC, 256, 0);
        lit_gather_kernel<<<NL, FM>>>(buf1, lh, xl);

        // literal LSTM (fused x/h GEMM)
        launch_tg(xl, 512, wp, oLWx, lh, 256, oLWh, L_b, zl, NL, 1024, 0);
        lstm_kernel<<<(NL * FM + 255) / 256, 256>>>(zl, lh, lc, NL);

        // vote + loss
        vote_concat_kernel<<<NV, FM>>>(lh, xv);
        launch_tg(xv, 512, wp, oVW0, nullptr, 0, 0, V_b0, v1, NV, 512, GF_RELU);
        launch_tg(v1, 512, wp, oVW1, nullptr, 0, 0, V_b1, v2, NV, 512, GF_RELU);
        vote_out_kernel<<<NV, 128>>>(v2, V_W2, V_b2);
        loss_kernel<<<(NC + 255) / 256, 256>>>();
    }

    finalize_kernel<<<(NV + 255) / 256, 256>>>((float*)d_out, out_size);
}

// round 8
// speedup vs baseline: 2.3466x; 1.0121x over previous
#include <cuda_runtime.h>
#include <cuda_bf16.h>
#include <math.h>
#include <stdint.h>

#define NV 4000
#define NL 8000          // 2*NV literals
#define NC 16800
#define NE 50400         // NC*3 edges
#define FM 256
#define ROUNDS 32

// ---------------------------------------------------------------------------
// PTX helpers (baseline ISA only: ldmatrix + mma.sync + cp.async, sm_80+)
// ---------------------------------------------------------------------------
__device__ __forceinline__ uint32_t smem_u32(const void* p) {
    uint32_t a;
    asm("{ .reg .u64 t; cvta.to.shared.u64 t, %1; cvt.u32.u64 %0, t; }"
        : "=r"(a) : "l"(p));
    return a;
}
__device__ __forceinline__ void ldsm_x4(uint32_t& r0, uint32_t& r1,
                                        uint32_t& r2, uint32_t& r3, uint32_t a) {
    asm volatile("ldmatrix.sync.aligned.m8n8.x4.shared.b16 {%0,%1,%2,%3}, [%4];"
                 : "=r"(r0), "=r"(r1), "=r"(r2), "=r"(r3) : "r"(a));
}
__device__ __forceinline__ void ldsm_x2(uint32_t& r0, uint32_t& r1, uint32_t a) {
    asm volatile("ldmatrix.sync.aligned.m8n8.x2.shared.b16 {%0,%1}, [%2];"
                 : "=r"(r0), "=r"(r1) : "r"(a));
}
__device__ __forceinline__ void mma_bf16(float* c, const uint32_t* a,
                                         const uint32_t* b) {
    asm volatile(
        "mma.sync.aligned.m16n8k16.row.col.f32.bf16.bf16.f32 "
        "{%0,%1,%2,%3}, {%4,%5,%6,%7}, {%8,%9}, {%0,%1,%2,%3};"
        : "+f"(c[0]), "+f"(c[1]), "+f"(c[2]), "+f"(c[3])
        : "r"(a[0]), "r"(a[1]), "r"(a[2]), "r"(a[3]), "r"(b[0]), "r"(b[1]));
}
__device__ __forceinline__ void cpasync16(uint32_t saddr, const void* g) {
    asm volatile("cp.async.cg.shared.global [%0], [%1], 16;"
                 :: "r"(saddr), "l"(g) : "memory");
}
#define CPASYNC_COMMIT() asm volatile("cp.async.commit_group;" ::: "memory")
#define CPASYNC_WAIT0()  asm volatile("cp.async.wait_group 0;" ::: "memory")

#define SWZ128(off) ((off) ^ (((off) >> 3) & 0x70))

// ---------------------------------------------------------------------------
// Scratch (static device globals)
// ---------------------------------------------------------------------------
__device__ float g_lh[NL * FM];
__device__ float g_lc[NL * FM];
__device__ float g_ch[NC * FM];
__device__ float g_cc[NC * FM];
__device__ float g_buf1[NC * FM];
__device__ float g_buf2[NC * FM];
__device__ float g_msgc[NC * FM];
__device__ float g_zc[NC * 4 * FM];
__device__ float g_msgl[NL * FM];
__device__ float g_zl[NL * 4 * FM];
__device__ float g_v1[NV * 2 * FM];
__device__ float g_v2[NV * 2 * FM];
__device__ float g_logits[NV];
__device__ float g_loss;

__device__ int g_lit[NE];
__device__ int g_cnt[NL];
__device__ int g_off[NL + 1];
__device__ int g_ledges[NE];

// weight pool: transposed [N,K] bf16, hi then lo halves
#define WTOT 2228224
__device__ __nv_bfloat16 g_wpool[2 * WTOT];

// ---------------------------------------------------------------------------
// Edge preprocessing (unchanged, known-correct)
// ---------------------------------------------------------------------------
__global__ void edge_prep_kernel(const int* __restrict__ lits) {
    int e = blockIdx.x * blockDim.x + threadIdx.x;
    if (e >= NE) return;
    int v = lits[e];
    int va = (v > 0 ? v : -v) - 1;
    g_lit[e] = (v > 0) ? va : (NV + va);
}
__global__ void zero_cnt_kernel() {
    int i = blockIdx.x * blockDim.x + threadIdx.x;
    if (i < NL) g_cnt[i] = 0;
}
__global__ void count_kernel() {
    int e = blockIdx.x * blockDim.x + threadIdx.x;
    if (e < NE) atomicAdd(&g_cnt[g_lit[e]], 1);
}
__global__ void scan_kernel() {
    __shared__ int part[1024];
    const int t = threadIdx.x;
    const int CH = 8;
    int base = t * CH;
    int local[CH];
    int s = 0;
    #pragma unroll
    for (int i = 0; i < CH; i++) {
        int idx = base + i;
        int v = (idx < NL) ? g_cnt[idx] : 0;
        local[i] = s;
        s += v;
    }
    part[t] = s;
    __syncthreads();
    for (int d = 1; d < 1024; d <<= 1) {
        int v = (t >= d) ? part[t - d] : 0;
        __syncthreads();
        part[t] += v;
        __syncthreads();
    }
    int off = (t == 0) ? 0 : part[t - 1];
    #pragma unroll
    for (int i = 0; i < CH; i++) {
        int idx = base + i;
        if (idx < NL) g_off[idx] = off + local[i];
    }
    if (t == 1023) g_off[NL] = part[1023];
}
__global__ void fill_kernel() {
    int e = blockIdx.x * blockDim.x + threadIdx.x;
    if (e >= NE) return;
    int l = g_lit[e];
    int pos = atomicAdd(&g_cnt[l], 1);
    g_ledges[g_off[l] + pos] = e;
}
__global__ void sort_kernel() {
    int l = blockIdx.x * blockDim.x + threadIdx.x;
    if (l >= NL) return;
    int beg = g_off[l], end = g_off[l + 1];
    for (int i = beg + 1; i < end; i++) {
        int key = g_ledges[i];
        int j = i - 1;
        while (j >= beg && g_ledges[j] > key) {
            g_ledges[j + 1] = g_ledges[j];
            j--;
        }
        g_ledges[j + 1] = key;
    }
}
__global__ void init_state_kernel(const float* __restrict__ Li,
                                  const float* __restrict__ Ci) {
    int idx = blockIdx.x * blockDim.x + threadIdx.x;
    const float inv = 0.0625f;
    if (idx < NL * FM) {
        g_lh[idx] = Li[idx & (FM - 1)] * inv;
        g_lc[idx] = 0.f;
    }
    if (idx < NC * FM) {
        g_ch[idx] = Ci[idx & (FM - 1)] * inv;
        g_cc[idx] = 0.f;
    }
    if (idx == 0) g_loss = 0.f;
}

// ---------------------------------------------------------------------------
// Weight split+transpose: src fp32 [K,N] -> pool hi/lo bf16 [N,K]
// ---------------------------------------------------------------------------
__global__ void wsplit_kernel(const float* __restrict__ src, int K, int N, int off) {
    int idx = blockIdx.x * blockDim.x + threadIdx.x;
    if (idx >= K * N) return;
    int k = idx / N, n = idx - k * N;
    float v = src[idx];
    __nv_bfloat16 h = __float2bfloat16_rn(v);
    __nv_bfloat16 l = __float2bfloat16_rn(v - __bfloat162float(h));
    g_wpool[off + (size_t)n * K + k] = h;
    g_wpool[WTOT + off + (size_t)n * K + k] = l;
}

// ---------------------------------------------------------------------------
// Pipelined tensor-core GEMM (mma.sync bf16, fp32 accum, Markidis 3-term):
//   C[M,N] = concat_K(A1,A2,A3) @ concat_rows(W1,W2,W3) (+bias)(relu)
// W pre-split transposed bf16 [N,K] hi/lo. Block 128x128, BK=64, double-buffered:
// B prefetched via cp.async, A prefetched into registers, split post-compute.
// GF_FLIP2: segment-2 rows are read flip-permuted (l<NV -> l+NV else l-NV).
// ---------------------------------------------------------------------------
#define GF_RELU 1
#define GF_FLIP2 4
#define TG_SMEM 131072

__global__ __launch_bounds__(256)
void tgemm_kernel(const float* __restrict__ A1, int K1,
                  const __nv_bfloat16* __restrict__ B1h,
                  const __nv_bfloat16* __restrict__ B1l,
                  const float* __restrict__ A2, int K2,
                  const __nv_bfloat16* __restrict__ B2h,
                  const __nv_bfloat16* __restrict__ B2l,
                  const float* __restrict__ A3, int K3,
                  const __nv_bfloat16* __restrict__ B3h,
                  const __nv_bfloat16* __restrict__ B3l,
                  const float* __restrict__ bias, float* __restrict__ C,
                  int M, int N, int flags) {
    extern __shared__ char smem[];
    // layout: ab0(32K: Ah+Al), ab1(32K), bb0(32K: Bh+Bl), bb1(32K)
    char* abp[2] = { smem, smem + 32768 };
    const uint32_t sb0 = smem_u32(smem);
    const uint32_t sab[2] = { sb0, sb0 + 32768 };
    const uint32_t sbb[2] = { sb0 + 65536, sb0 + 98304 };

    const int tid = threadIdx.x;
    const int wid = tid >> 5, lid = tid & 31;
    const int bm = blockIdx.y * 128;
    const int bn = blockIdx.x * 128;
    const int wm = (wid & 1) * 64;
    const int wn = (wid >> 1) * 32;

    float acc[4][4][4];
    #pragma unroll
    for (int i = 0; i < 4; i++)
        #pragma unroll
        for (int j = 0; j < 4; j++)
            #pragma unroll
            for (int q = 0; q < 4; q++) acc[i][j][q] = 0.f;

    const int nch = (K1 + K2 + K3) >> 6;
    float4 va[8];

    // ---- helpers (macros expanded inline for tight codegen) ----
    #define LOAD_A_REGS(c)  do {                                               \
        int kk = (c) << 6;                                                     \
        const float* A = A1; int ldk = K1; int flip = 0;                       \
        if (kk >= K1 + K2) { A = A3; ldk = K3; kk -= K1 + K2; }                \
        else if (kk >= K1) { A = A2; ldk = K2; kk -= K1;                       \
                             flip = (flags & GF_FLIP2); }                      \
        _Pragma("unroll")                                                      \
        for (int i = 0; i < 8; i++) {                                          \
            int idx = i * 256 + tid;                                           \
            int row = idx >> 4;                                                \
            int c4 = (idx & 15) << 2;                                          \
            int gr = bm + row;                                                 \
            va[i] = make_float4(0.f, 0.f, 0.f, 0.f);                           \
            if (gr < M) {                                                      \
                int ar = flip ? (gr < NV ? gr + NV : gr - NV) : gr;            \
                va[i] = *(const float4*)&A[(size_t)ar * ldk + kk + c4];        \
            }                                                                  \
        }                                                                      \
    } while (0)

    #define STORE_A(buf) do {                                                  \
        char* dst = abp[buf];                                                  \
        _Pragma("unroll")                                                      \
        for (int i = 0; i < 8; i++) {                                          \
            int idx = i * 256 + tid;                                           \
            int row = idx >> 4;                                                \
            int c4 = (idx & 15) << 2;                                          \
            float4 v = va[i];                                                  \
            __nv_bfloat16 h0 = __float2bfloat16_rn(v.x);                       \
            __nv_bfloat16 h1 = __float2bfloat16_rn(v.y);                       \
            __nv_bfloat16 h2 = __float2bfloat16_rn(v.z);                       \
            __nv_bfloat16 h3 = __float2bfloat16_rn(v.w);                       \
            __nv_bfloat162 hp0 = __halves2bfloat162(h0, h1);                   \
            __nv_bfloat162 hp1 = __halves2bfloat162(h2, h3);                   \
            __nv_bfloat162 lp0 = __halves2bfloat162(                           \
                __float2bfloat16_rn(v.x - __bfloat162float(h0)),               \
                __float2bfloat16_rn(v.y - __bfloat162float(h1)));              \
            __nv_bfloat162 lp1 = __halves2bfloat162(                           \
                __float2bfloat16_rn(v.z - __bfloat162float(h2)),               \
                __float2bfloat16_rn(v.w - __bfloat162float(h3)));              \
            uint32_t off = SWZ128((uint32_t)(row * 128 + c4 * 2));             \
            *(uint2*)(dst + off) =                                             \
                make_uint2(*(uint32_t*)&hp0, *(uint32_t*)&hp1);                \
            *(uint2*)(dst + 16384 + off) =                                     \
                make_uint2(*(uint32_t*)&lp0, *(uint32_t*)&lp1);                \
        }                                                                      \
    } while (0)

    #define CPASYNC_B(c, buf) do {                                             \
        int kk = (c) << 6;                                                     \
        const __nv_bfloat16 *bh = B1h, *bl = B1l; int ldk = K1;                \
        if (kk >= K1 + K2) { bh = B3h; bl = B3l; ldk = K3; kk -= K1 + K2; }    \
        else if (kk >= K1) { bh = B2h; bl = B2l; ldk = K2; kk -= K1; }         \
        _Pragma("unroll")                                                      \
        for (int i = 0; i < 8; i++) {                                          \
            int idx = i * 256 + tid;                                           \
            int half = idx >> 10;                                              \
            int j = idx & 1023;                                                \
            int row = j >> 3;                                                  \
            int c16 = (j & 7) << 4;                                            \
            const __nv_bfloat16* src =                                         \
                (half ? bl : bh) + (size_t)(bn + row) * ldk + kk + (c16 >> 1); \
            cpasync16(sbb[buf] + half * 16384 +                                \
                      SWZ128((uint32_t)(row * 128 + c16)), src);               \
        }                                                                      \
    } while (0)

    // ---- prologue ----
    LOAD_A_REGS(0);
    CPASYNC_B(0, 0);
    CPASYNC_COMMIT();
    STORE_A(0);
    CPASYNC_WAIT0();
    __syncthreads();

    // ---- pipelined main loop ----
    for (int c = 0; c < nch; c++) {
        int cur = c & 1, nxt = cur ^ 1;
        if (c + 1 < nch) {
            LOAD_A_REGS(c + 1);
            CPASYNC_B(c + 1, nxt);
            CPASYNC_COMMIT();
        }

        const uint32_t sAh = sab[cur], sAl = sab[cur] + 16384;
        const uint32_t sBh = sbb[cur], sBl = sbb[cur] + 16384;
        #pragma unroll
        for (int s = 0; s < 4; s++) {
            int kb = s * 32;
            uint32_t ah[4][4], al[4][4], bhf[4][2], blf[4][2];
            int arow = (lid & 15);
            int acolb = kb + (lid >> 4) * 16;
            #pragma unroll
            for (int mt = 0; mt < 4; mt++) {
                uint32_t o = SWZ128((uint32_t)((wm + mt * 16 + arow) * 128 + acolb));
                ldsm_x4(ah[mt][0], ah[mt][1], ah[mt][2], ah[mt][3], sAh + o);
                ldsm_x4(al[mt][0], al[mt][1], al[mt][2], al[mt][3], sAl + o);
            }
            int brow = (lid & 7);
            int bcolb = kb + ((lid >> 3) & 1) * 16;
            #pragma unroll
            for (int nt = 0; nt < 4; nt++) {
                uint32_t o = SWZ128((uint32_t)((wn + nt * 8 + brow) * 128 + bcolb));
                ldsm_x2(bhf[nt][0], bhf[nt][1], sBh + o);
                ldsm_x2(blf[nt][0], blf[nt][1], sBl + o);
            }
            #pragma unroll
            for (int mt = 0; mt < 4; mt++)
                #pragma unroll
                for (int nt = 0; nt < 4; nt++) {
                    mma_bf16(acc[mt][nt], ah[mt], bhf[nt]);
                    mma_bf16(acc[mt][nt], al[mt], bhf[nt]);
                    mma_bf16(acc[mt][nt], ah[mt], blf[nt]);
                }
        }

        if (c + 1 < nch) {
            STORE_A(nxt);
            CPASYNC_WAIT0();
        }
        __syncthreads();
    }

    // ---- epilogue: direct float2 stores with bias/relu ----
    #pragma unroll
    for (int mt = 0; mt < 4; mt++) {
        int r0 = bm + wm + mt * 16 + (lid >> 2);
        #pragma unroll
        for (int nt = 0; nt < 4; nt++) {
            int col = bn + wn + nt * 8 + (lid & 3) * 2;
            float bx = 0.f, by = 0.f;
            if (bias) { bx = bias[col]; by = bias[col + 1]; }
            float2 v0 = make_float2(acc[mt][nt][0] + bx, acc[mt][nt][1] + by);
            float2 v1 = make_float2(acc[mt][nt][2] + bx, acc[mt][nt][3] + by);
            if (flags & GF_RELU) {
                v0.x = fmaxf(v0.x, 0.f); v0.y = fmaxf(v0.y, 0.f);
                v1.x = fmaxf(v1.x, 0.f); v1.y = fmaxf(v1.y, 0.f);
            }
            if (r0 < M)     *(float2*)&C[(size_t)r0 * N + col] = v0;
            if (r0 + 8 < M) *(float2*)&C[(size_t)(r0 + 8) * N + col] = v1;
        }
    }
}

// ---------------------------------------------------------------------------
// Elementwise / gather kernels
// ---------------------------------------------------------------------------
__device__ __forceinline__ float sigm(float x) { return 1.f / (1.f + expf(-x)); }

__global__ void lstm_kernel(const float* __restrict__ z,
                            float* __restrict__ h, float* __restrict__ c, int R) {
    int idx = blockIdx.x * blockDim.x + threadIdx.x;
    if (idx >= R * FM) return;
    int r = idx / FM, f = idx - r * FM;
    const float* zr = z + (size_t)r * 4 * FM;
    float zi = zr[f], zf = zr[FM + f], zg = zr[2 * FM + f], zo = zr[3 * FM + f];
    float cv = sigm(zf) * c[idx] + sigm(zi) * tanhf(zg);
    c[idx] = cv;
    h[idx] = sigm(zo) * tanhf(cv);
}

__global__ void clause_gather_kernel(const float* __restrict__ pre,
                                     float* __restrict__ out) {
    int c = blockIdx.x;
    int f = threadIdx.x;
    int e0 = c * 3;
    float s = pre[(size_t)g_lit[e0] * FM + f] +
              pre[(size_t)g_lit[e0 + 1] * FM + f] +
              pre[(size_t)g_lit[e0 + 2] * FM + f];
    out[(size_t)c * FM + f] = s;
}

// msgl[l] = sum_{edges of l} cl_pre[clause(e)]   (256-wide only; no concat)
__global__ void lit_gather_kernel(const float* __restrict__ cl_pre,
                                  float* __restrict__ msgl) {
    int l = blockIdx.x;
    int f = threadIdx.x;
    int beg = g_off[l], end = g_off[l + 1];
    float s = 0.f;
    for (int i = beg; i < end; i++) {
        int e = g_ledges[i];
        s += cl_pre[(size_t)(e / 3) * FM + f];
    }
    msgl[(size_t)l * FM + f] = s;
}

__global__ void vote_out_kernel(const float* __restrict__ H,
                                const float* __restrict__ W,
                                const float* __restrict__ b) {
    int r = blockIdx.x;
    float s = 0.f;
    for (int k = threadIdx.x; k < 2 * FM; k += blockDim.x)
        s += H[(size_t)r * 2 * FM + k] * W[k];
    for (int o = 16; o; o >>= 1) s += __shfl_down_sync(0xffffffffu, s, o);
    __shared__ float sm[4];
    if ((threadIdx.x & 31) == 0) sm[threadIdx.x >> 5] = s;
    __syncthreads();
    if (threadIdx.x == 0)
        g_logits[r] = sm[0] + sm[1] + sm[2] + sm[3] + b[0];
}

__device__ __forceinline__ float softplus_f(float x) {
    return x > 0.f ? x + log1pf(expf(-x)) : log1pf(expf(x));
}

__global__ void loss_kernel() {
    int c = blockIdx.x * blockDim.x + threadIdx.x;
    float t = 0.f;
    if (c < NC) {
        float s = 0.f;
        #pragma unroll
        for (int k = 0; k < 3; k++) {
            int lit = g_lit[c * 3 + k];
            float sign = (lit < NV) ? 1.f : -1.f;
            int var = (lit < NV) ? lit : lit - NV;
            s += softplus_f(g_logits[var] * sign);
        }
        float cv = expf(-s);
        float l = -logf(1.f - cv + 1e-8f);
        t = l * l;
    }
    for (int o = 16; o; o >>= 1) t += __shfl_down_sync(0xffffffffu, t, o);
    __shared__ float sm[8];
    if ((threadIdx.x & 31) == 0) sm[threadIdx.x >> 5] = t;
    __syncthreads();
    if (threadIdx.x < 8) {
        float v = sm[threadIdx.x];
        for (int o = 4; o; o >>= 1) v += __shfl_down_sync(0xffu, v, o);
        if (threadIdx.x == 0) atomicAdd(&g_loss, v);
    }
}

__global__ void finalize_kernel(float* __restrict__ out, int out_size) {
    int i = blockIdx.x * blockDim.x + threadIdx.x;
    if (i < NV && i < out_size) out[i] = g_logits[i];
    if (i == 0 && out_size > NV) out[NV] = g_loss / (float)ROUNDS;
}

// ---------------------------------------------------------------------------
// Host orchestration
// ---------------------------------------------------------------------------
static const __nv_bfloat16* g_wp_host;

static inline void launch_tg(const float* A1, int K1, int off1,
                             const float* A2, int K2, int off2,
                             const float* A3, int K3, int off3,
                             const float* bias, float* C, int M, int N, int flags) {
    const __nv_bfloat16* wp = g_wp_host;
    dim3 grid(N / 128, (M + 127) / 128);
    tgemm_kernel<<<grid, 256, TG_SMEM>>>(
        A1, K1, wp + off1, wp + WTOT + off1,
        A2, K2, A2 ? wp + off2 : nullptr, A2 ? wp + WTOT + off2 : nullptr,
        A3, K3, A3 ? wp + off3 : nullptr, A3 ? wp + WTOT + off3 : nullptr,
        bias, C, M, N, flags);
}

extern "C" void kernel_launch(void* const* d_in, const int* in_sizes, int n_in,
                              void* d_out, int out_size) {
    int base = (n_in >= 2 && in_sizes[1] == 1) ? 1 : 0;
    const int* clause_lits = (const int*)d_in[0];
    const float* P[26];
    for (int i = 0; i < 26; i++) P[i] = (const float*)d_in[1 + base + i];
    const float *L_init = P[0], *C_init = P[1];
    const float *LC_W0 = P[2], *LC_b0 = P[3], *LC_W1 = P[4], *LC_b1 = P[5],
                *LC_W2 = P[6], *LC_b2 = P[7];
    const float *CL_W0 = P[8], *CL_b0 = P[9], *CL_W1 = P[10], *CL_b1 = P[11],
                *CL_W2 = P[12], *CL_b2 = P[13];
    const float *C_Wx = P[14], *C_Wh = P[15], *C_b = P[16];
    const float *L_Wx = P[17], *L_Wh = P[18], *L_b = P[19];
    const float *V_W0 = P[20], *V_b0 = P[21], *V_W1 = P[22], *V_b1 = P[23],
                *V_W2 = P[24], *V_b2 = P[25];

    float *lh, *lc, *ch, *cc, *buf1, *buf2, *msgc, *zc, *msgl, *zl, *v1, *v2;
    __nv_bfloat16* wp;
    cudaGetSymbolAddress((void**)&lh, g_lh);
    cudaGetSymbolAddress((void**)&lc, g_lc);
    cudaGetSymbolAddress((void**)&ch, g_ch);
    cudaGetSymbolAddress((void**)&cc, g_cc);
    cudaGetSymbolAddress((void**)&buf1, g_buf1);
    cudaGetSymbolAddress((void**)&buf2, g_buf2);
    cudaGetSymbolAddress((void**)&msgc, g_msgc);
    cudaGetSymbolAddress((void**)&zc, g_zc);
    cudaGetSymbolAddress((void**)&msgl, g_msgl);
    cudaGetSymbolAddress((void**)&zl, g_zl);
    cudaGetSymbolAddress((void**)&v1, g_v1);
    cudaGetSymbolAddress((void**)&v2, g_v2);
    cudaGetSymbolAddress((void**)&wp, g_wpool);
    g_wp_host = wp;

    cudaFuncSetAttribute(tgemm_kernel, cudaFuncAttributeMaxDynamicSharedMemorySize,
                         TG_SMEM);

    // weight pool offsets ([N,K] transposed, element offsets)
    const int oLC0 = 0, oLC1 = 65536, oLC2 = 131072;
    const int oCL0 = 196608, oCL1 = 262144, oCL2 = 327680;
    const int oCWx = 393216, oCWh = 655360;
    const int oLWxa = 917504, oLWxb = 1179648, oLWh = 1441792;
    const int oVW0a = 1703936, oVW0b = 1835008, oVW1 = 1966080;

    struct { const float* src; int K, N, off; } WS[14] = {
        {LC_W0, 256, 256, oLC0}, {LC_W1, 256, 256, oLC1}, {LC_W2, 256, 256, oLC2},
        {CL_W0, 256, 256, oCL0}, {CL_W1, 256, 256, oCL1}, {CL_W2, 256, 256, oCL2},
        {C_Wx, 256, 1024, oCWx}, {C_Wh, 256, 1024, oCWh},
        {L_Wx, 256, 1024, oLWxa}, {L_Wx + 256 * 1024, 256, 1024, oLWxb},
        {L_Wh, 256, 1024, oLWh},
        {V_W0, 256, 512, oVW0a}, {V_W0 + 256 * 512, 256, 512, oVW0b},
        {V_W1, 512, 512, oVW1},
    };
    for (int i = 0; i < 14; i++) {
        int n = WS[i].K * WS[i].N;
        wsplit_kernel<<<(n + 255) / 256, 256>>>(WS[i].src, WS[i].K, WS[i].N,
                                                WS[i].off);
    }

    // preprocessing
    edge_prep_kernel<<<(NE + 255) / 256, 256>>>(clause_lits);
    zero_cnt_kernel<<<(NL + 255) / 256, 256>>>();
    count_kernel<<<(NE + 255) / 256, 256>>>();
    scan_kernel<<<1, 1024>>>();
    zero_cnt_kernel<<<(NL + 255) / 256, 256>>>();
    fill_kernel<<<(NE + 255) / 256, 256>>>();
    sort_kernel<<<(NL + 127) / 128, 128>>>();
    init_state_kernel<<<(NC * FM + 255) / 256, 256>>>(L_init, C_init);

    for (int r = 0; r < ROUNDS; r++) {
        // literal -> clause MLP
        launch_tg(lh, 256, oLC0, nullptr, 0, 0, nullptr, 0, 0,
                  LC_b0, buf1, NL, 256, GF_RELU);
        launch_tg(buf1, 256, oLC1, nullptr, 0, 0, nullptr, 0, 0,
                  LC_b1, buf2, NL, 256, GF_RELU);
        launch_tg(buf2, 256, oLC2, nullptr, 0, 0, nullptr, 0, 0,
                  LC_b2, buf1, NL, 256, 0);
        clause_gather_kernel<<<NC, FM>>>(buf1, msgc);

        // clause LSTM (fused x/h GEMM, K=512)
        launch_tg(msgc, 256, oCWx, ch, 256, oCWh, nullptr, 0, 0,
                  C_b, zc, NC, 1024, 0);
        lstm_kernel<<<(NC * FM + 255) / 256, 256>>>(zc, ch, cc, NC);

        // clause -> literal MLP
        launch_tg(ch, 256, oCL0, nullptr, 0, 0, nullptr, 0, 0,
                  CL_b0, buf1, NC, 256, GF_RELU);
        launch_tg(buf1, 256, oCL1, nullptr, 0, 0, nullptr, 0, 0,
                  CL_b1, buf2, NC, 256, GF_RELU);
        launch_tg(buf2, 256, oCL2, nullptr, 0, 0, nullptr, 0, 0,
                  CL_b2, buf1, NC, 256, 0);
        lit_gather_kernel<<<NL, FM>>>(buf1, msgl);

        // literal LSTM: z = [msgl, flipped(lh), lh] @ rows(LWxa, LWxb, LWh)
        launch_tg(msgl, 256, oLWxa, lh, 256, oLWxb, lh, 256, oLWh,
                  L_b, zl, NL, 1024, GF_FLIP2);
        lstm_kernel<<<(NL * FM + 255) / 256, 256>>>(zl, lh, lc, NL);

        // vote: x = [lh[:NV], lh[NV:]] along K (no concat materialization)
        launch_tg(lh, 256, oVW0a, lh + (size_t)NV * FM, 256, oVW0b, nullptr, 0, 0,
                  V_b0, v1, NV, 512, GF_RELU);
        launch_tg(v1, 512, oVW1, nullptr, 0, 0, nullptr, 0, 0,
                  V_b1, v2, NV, 512, GF_RELU);
        vote_out_kernel<<<NV, 128>>>(v2, V_W2, V_b2);
        loss_kernel<<<(NC + 255) / 256, 256>>>();
    }

    finalize_kernel<<<(NV + 255) / 256, 256>>>((float*)d_out, out_size);
}